// round 10
// baseline (speedup 1.0000x reference)
#include <cuda_runtime.h>
#include <cuda_fp16.h>
#include <cstdint>

#define Bb 2
#define Tt 4096
#define Hh 8
#define Dd 32
#define HD 256
#define XD 128
#define TOKD 64
#define BT (Bb*Tt)

// zero coverage: g_O (BT*HD floats) + g_L (BT*Hh floats), in float4 units
#define NZERO_F4 ((BT*HD + BT*Hh) / 4)          // 540672
#define NZERO_BLK ((NZERO_F4 + 255) / 256)      // 2112

__device__ __half g_Qh[Bb*Hh*Tt*Dd];
__device__ __half g_Kh[Bb*Hh*Tt*Dd];
__device__ __half g_Vt[Bb*Hh*Dd*Tt];
__device__ float  g_O[BT*HD];
__device__ float  g_L[BT*Hh];
__device__ __half g_WoT[HD*HD];

__device__ __forceinline__ uint32_t pack_h2(float lo, float hi) {
    __half2 h = __floats2half2_rn(lo, hi);
    return *reinterpret_cast<uint32_t*>(&h);
}
__device__ __forceinline__ uint32_t h2exp2(uint32_t x) {
    uint32_t y;
    asm("ex2.approx.f16x2 %0, %1;" : "=r"(y) : "r"(x));
    return y;
}
__device__ __forceinline__ float frcp(float x) {
    float y;
    asm("rcp.approx.ftz.f32 %0, %1;" : "=f"(y) : "f"(x));
    return y;
}
__device__ __forceinline__ void mma_f16(float* d, const uint32_t* a, const uint32_t* b) {
    asm volatile(
        "mma.sync.aligned.m16n8k16.row.col.f32.f16.f16.f32 "
        "{%0,%1,%2,%3}, {%4,%5,%6,%7}, {%8,%9}, {%0,%1,%2,%3};"
        : "+f"(d[0]), "+f"(d[1]), "+f"(d[2]), "+f"(d[3])
        : "r"(a[0]), "r"(a[1]), "r"(a[2]), "r"(a[3]), "r"(b[0]), "r"(b[1]));
}
__device__ __forceinline__ void ldsm4(uint32_t& r0, uint32_t& r1, uint32_t& r2, uint32_t& r3,
                                      uint32_t addr) {
    asm volatile("ldmatrix.sync.aligned.m8n8.x4.shared.b16 {%0,%1,%2,%3}, [%4];"
                 : "=r"(r0), "=r"(r1), "=r"(r2), "=r"(r3) : "r"(addr));
}
__device__ __forceinline__ uint32_t smem_u32(const void* p) {
    uint32_t a;
    asm("{ .reg .u64 t; cvta.to.shared.u64 t, %1; cvt.u32.u64 %0, t; }" : "=r"(a) : "l"(p));
    return a;
}
__device__ __forceinline__ void cp16(uint32_t d, const void* s) {
    asm volatile("cp.async.cg.shared.global [%0], [%1], 16;" :: "r"(d), "l"(s));
}
#define CP_COMMIT() asm volatile("cp.async.commit_group;" ::: "memory")
#define CP_WAIT0()  asm volatile("cp.async.wait_group 0;" ::: "memory")
#define CP_WAIT1()  asm volatile("cp.async.wait_group 1;" ::: "memory")

// ---------------------------------------------------------------------------
// Kernel 0: zero O/L accumulators + transpose Wo into g_WoT (half).
// blocks [0, NZERO_BLK): zeroing; blocks [NZERO_BLK, NZERO_BLK+64): transpose.
// ---------------------------------------------------------------------------
__global__ __launch_bounds__(256) void prep_kernel(const float* __restrict__ Wo)
{
    __shared__ __half t[32][34];
    const unsigned bid = blockIdx.x;
    const int tid = threadIdx.x;

    if (bid < (unsigned)NZERO_BLK) {
        const unsigned i = bid * 256u + tid;
        const float4 z = make_float4(0.f, 0.f, 0.f, 0.f);
        if (i < (BT * HD / 4)) reinterpret_cast<float4*>(g_O)[i] = z;
        else if (i < NZERO_F4) reinterpret_cast<float4*>(g_L)[i - BT * HD / 4] = z;
        return;
    }
    const int b2 = bid - NZERO_BLK;
    const int bx = (b2 & 7) * 32, by = (b2 >> 3) * 32;
    for (int i = tid; i < 1024; i += 256) {
        int r = i >> 5, c = i & 31;
        t[r][c] = __float2half_rn(Wo[(size_t)(by + r) * HD + bx + c]);
    }
    __syncthreads();
    for (int i = tid; i < 1024; i += 256) {
        int r = i >> 5, c = i & 31;
        g_WoT[(size_t)(bx + r) * HD + by + c] = t[c][r];
    }
}

// ---------------------------------------------------------------------------
// Kernel 1: projections via fp16 m16n8k16.
// ---------------------------------------------------------------------------
__global__ __launch_bounds__(256) void proj_mma_kernel(
    const float* __restrict__ x,
    const float* __restrict__ Wq,
    const float* __restrict__ Wk,
    const float* __restrict__ Wv)
{
    extern __shared__ __half psm[];
    __half* Xh  = psm;               // [256][72]
    __half* Wst = psm + 256 * 72;    // [64 n][72 k]

    const int z = blockIdx.z;
    const float* __restrict__ W = (z == 0) ? Wq : (z == 1) ? Wk : Wv;
    const int xoff = (z == 2) ? 0 : TOKD;

    const int m0 = blockIdx.x * 256;
    const int n0 = blockIdx.y * 64;

    const int tid  = threadIdx.x;
    const int wid  = tid >> 5;
    const int lane = tid & 31;
    const int gq   = lane >> 2;
    const int l    = lane & 3;

    for (int i = tid; i < 256 * 16; i += 256) {
        int r = i >> 4, c4 = (i & 15) * 4;
        float4 v = *reinterpret_cast<const float4*>(&x[(size_t)(m0 + r) * XD + xoff + c4]);
        uint2 u = make_uint2(pack_h2(v.x, v.y), pack_h2(v.z, v.w));
        *reinterpret_cast<uint2*>(&Xh[r * 72 + c4]) = u;
    }
    for (int i = tid; i < 64 * 16; i += 256) {
        int k = i >> 4, n4 = (i & 15) * 4;
        float4 w = *reinterpret_cast<const float4*>(&W[(size_t)k * HD + n0 + n4]);
        Wst[(n4 + 0) * 72 + k] = __float2half_rn(w.x);
        Wst[(n4 + 1) * 72 + k] = __float2half_rn(w.y);
        Wst[(n4 + 2) * 72 + k] = __float2half_rn(w.z);
        Wst[(n4 + 3) * 72 + k] = __float2half_rn(w.w);
    }
    __syncthreads();

    float sc[2][8][4] = {};
    const int rb = wid * 32;
#pragma unroll
    for (int ks = 0; ks < 4; ks++) {
        const int kk = ks * 16 + 2 * l;
        uint32_t b[8][2];
#pragma unroll
        for (int nt = 0; nt < 8; nt++) {
            b[nt][0] = *reinterpret_cast<const uint32_t*>(&Wst[(nt * 8 + gq) * 72 + kk]);
            b[nt][1] = *reinterpret_cast<const uint32_t*>(&Wst[(nt * 8 + gq) * 72 + kk + 8]);
        }
#pragma unroll
        for (int mt = 0; mt < 2; mt++) {
            const int r0 = rb + mt * 16;
            uint32_t a[4];
            a[0] = *reinterpret_cast<const uint32_t*>(&Xh[(r0 + gq) * 72 + kk]);
            a[1] = *reinterpret_cast<const uint32_t*>(&Xh[(r0 + 8 + gq) * 72 + kk]);
            a[2] = *reinterpret_cast<const uint32_t*>(&Xh[(r0 + gq) * 72 + kk + 8]);
            a[3] = *reinterpret_cast<const uint32_t*>(&Xh[(r0 + 8 + gq) * 72 + kk + 8]);
#pragma unroll
            for (int nt = 0; nt < 8; nt++) mma_f16(sc[mt][nt], a, b[nt]);
        }
    }

    if (z == 0) {
        const float qs = 0.17677669529663687f * 1.4426950408889634f;
#pragma unroll
        for (int mt = 0; mt < 2; mt++)
#pragma unroll
            for (int nt = 0; nt < 8; nt++)
#pragma unroll
                for (int e = 0; e < 4; e++) sc[mt][nt][e] *= qs;
    }

    if (z < 2) {
        __half* __restrict__ gh = (z == 0) ? g_Qh : g_Kh;
#pragma unroll
        for (int mt = 0; mt < 2; mt++) {
            const int m = m0 + rb + mt * 16 + gq;
            const int b0 = m >> 12, t0 = m & (Tt - 1);
            const int t1 = (m + 8) & (Tt - 1);
#pragma unroll
            for (int nt = 0; nt < 8; nt++) {
                const int n = n0 + nt * 8 + 2 * l;
                const int h = n >> 5, d = n & 31;
                __half2 w0 = __floats2half2_rn(sc[mt][nt][0], sc[mt][nt][1]);
                __half2 w1 = __floats2half2_rn(sc[mt][nt][2], sc[mt][nt][3]);
                *reinterpret_cast<__half2*>(&gh[(((size_t)(b0 * Hh + h)) * Tt + t0) * Dd + d]) = w0;
                *reinterpret_cast<__half2*>(&gh[(((size_t)(b0 * Hh + h)) * Tt + t1) * Dd + d]) = w1;
            }
        }
    } else {
#pragma unroll
        for (int mt = 0; mt < 2; mt++) {
            const int m = m0 + rb + mt * 16 + gq;
            const int b0 = m >> 12, t0 = m & (Tt - 1);
            const int t1 = (m + 8) & (Tt - 1);
#pragma unroll
            for (int nt = 0; nt < 8; nt++) {
                const int n = n0 + nt * 8 + 2 * l;
                const int h = n >> 5, d = n & 31;
                __half* base = &g_Vt[(size_t)(b0 * Hh + h) * Dd * Tt];
                base[(size_t)(d    ) * Tt + t0] = __float2half_rn(sc[mt][nt][0]);
                base[(size_t)(d + 1) * Tt + t0] = __float2half_rn(sc[mt][nt][1]);
                base[(size_t)(d    ) * Tt + t1] = __float2half_rn(sc[mt][nt][2]);
                base[(size_t)(d + 1) * Tt + t1] = __float2half_rn(sc[mt][nt][3]);
            }
        }
    }
}

// ---------------------------------------------------------------------------
// Kernel 2: chunked fp16 attention, 256 threads = 8 warps x 16 q-rows.
// ---------------------------------------------------------------------------
__global__ __launch_bounds__(256, 2) void attn_mma_kernel()
{
    extern __shared__ __half hsm[];
    __half* Qs  = hsm;                 // [128][40]  (80B rows)
    __half* KsB = hsm + 128 * 40;      // 2 x [64][40]
    __half* VtB = KsB + 2 * 64 * 40;   // 2 x [32][72] (144B rows)

    const int cid = 79 - blockIdx.x;
    int qt, ch;
    if (cid < 8)       { qt = cid;                 ch = 0; }
    else if (cid < 24) { qt = 8 + ((cid - 8) >> 1);  ch = (cid - 8) & 1; }
    else if (cid < 48) { qt = 16 + (cid - 24) / 3;   ch = (cid - 24) % 3; }
    else               { qt = 24 + ((cid - 48) >> 2); ch = (cid - 48) & 3; }

    const int bh = blockIdx.y;
    const int q0 = qt * 128;
    const int nkv = 2 * qt + 2;
    const int ntiles = min(16, nkv - ch * 16);

    const __half* __restrict__ Qp = g_Qh + (size_t)bh * Tt * Dd;
    const __half* __restrict__ Kp = g_Kh + (size_t)bh * Tt * Dd;
    const __half* __restrict__ Vp = g_Vt + (size_t)bh * Dd * Tt;

    const int tid  = threadIdx.x;
    const int wid  = tid >> 5;
    const int lane = tid & 31;
    const int gq   = lane >> 2;
    const int l    = lane & 3;
    const int r8   = lane & 7;
    const int qg   = lane >> 3;

    const uint32_t qs_addr = smem_u32(Qs);
    const uint32_t ks_addr = smem_u32(KsB);
    const uint32_t vt_addr = smem_u32(VtB);

    const uint32_t qrow_off = (uint32_t)(((qg & 1) * 8 + r8) * 80 + (qg >> 1) * 16);
    const uint32_t krow_off = (uint32_t)(((qg >> 1) * 8 + r8) * 80 + (qg & 1) * 16);
    const uint32_t vrow_off = (uint32_t)(((qg >> 1) * 8 + r8) * 144 + (qg & 1) * 16);

    // Q stage
    for (int i = tid; i < 128 * 4; i += 256) {
        int r = i >> 2, seg = i & 3;
        uint4 v = *reinterpret_cast<const uint4*>(&Qp[(size_t)(q0 + r) * Dd + seg * 8]);
        *reinterpret_cast<uint4*>(&Qs[r * 40 + seg * 8]) = v;
    }

    // prefetch tile 0 -> buf 0
    {
        const int k0 = (ch * 16) * 64;
        int row = tid >> 2, seg = tid & 3;
        cp16(ks_addr + row * 80 + seg * 16, Kp + (size_t)(k0 + row) * Dd + seg * 8);
        int d = tid >> 3, seg8 = tid & 7;
        cp16(vt_addr + d * 144 + seg8 * 16, Vp + (size_t)d * Tt + k0 + seg8 * 8);
        CP_COMMIT();
    }

    __syncthreads();   // Q visible

    uint32_t qa[2][4];
#pragma unroll
    for (int ks = 0; ks < 2; ks++)
        ldsm4(qa[ks][0], qa[ks][1], qa[ks][2], qa[ks][3],
              qs_addr + (wid * 16) * 80 + qrow_off + ks * 32);

    const uint32_t bone = (gq == 0) ? 0x3C003C00u : 0u;
    const uint32_t bones[2] = { bone, bone };

    float oacc[5][4] = {};
    const int rowb = q0 + wid * 16;

    for (int it = 0; it < ntiles; it++) {
        __syncthreads();
        if (it + 1 < ntiles) {
            const int k0n = (ch * 16 + it + 1) * 64;
            const int buf = (it + 1) & 1;
            int row = tid >> 2, seg = tid & 3;
            cp16(ks_addr + buf * 5120 + row * 80 + seg * 16,
                 Kp + (size_t)(k0n + row) * Dd + seg * 8);
            int d = tid >> 3, seg8 = tid & 7;
            cp16(vt_addr + buf * 4608 + d * 144 + seg8 * 16,
                 Vp + (size_t)d * Tt + k0n + seg8 * 8);
            CP_COMMIT();
            CP_WAIT1();
        } else {
            CP_WAIT0();
        }
        __syncthreads();

        const int k0 = (ch * 16 + it) * 64;
        const uint32_t kb = ks_addr + (it & 1) * 5120 + krow_off;
        const uint32_t vb = vt_addr + (it & 1) * 4608 + vrow_off;

        // ---- S = Q @ K^T
        float sc[8][4] = {};
#pragma unroll
        for (int ks = 0; ks < 2; ks++) {
            uint32_t bk[8][2];
#pragma unroll
            for (int p = 0; p < 4; p++)
                ldsm4(bk[2 * p][0], bk[2 * p][1], bk[2 * p + 1][0], bk[2 * p + 1][1],
                      kb + p * 1280 + ks * 32);
#pragma unroll
            for (int nt = 0; nt < 8; nt++) mma_f16(sc[nt], qa[ks], bk[nt]);
        }

        // ---- softmax: p = 2^s via f16x2
        uint32_t ph[2][8];
        if (k0 + 63 <= rowb) {
#pragma unroll
            for (int nt = 0; nt < 8; nt++) {
                ph[0][nt] = h2exp2(pack_h2(sc[nt][0], sc[nt][1]));
                ph[1][nt] = h2exp2(pack_h2(sc[nt][2], sc[nt][3]));
            }
        } else {
            const int r0 = rowb + gq, r1 = rowb + 8 + gq;
#pragma unroll
            for (int nt = 0; nt < 8; nt++) {
                const int c0 = k0 + nt * 8 + 2 * l;
                float f0 = (c0     <= r0) ? sc[nt][0] : -1e30f;
                float f1 = (c0 + 1 <= r0) ? sc[nt][1] : -1e30f;
                float f2 = (c0     <= r1) ? sc[nt][2] : -1e30f;
                float f3 = (c0 + 1 <= r1) ? sc[nt][3] : -1e30f;
                ph[0][nt] = h2exp2(pack_h2(f0, f1));
                ph[1][nt] = h2exp2(pack_h2(f2, f3));
            }
        }

        // ---- O += P @ [V | 1]
#pragma unroll
        for (int ks = 0; ks < 4; ks++) {
            uint32_t bv[4][2];
#pragma unroll
            for (int p = 0; p < 2; p++)
                ldsm4(bv[2 * p][0], bv[2 * p][1], bv[2 * p + 1][0], bv[2 * p + 1][1],
                      vb + p * 2304 + ks * 32);
            uint32_t a[4];
            a[0] = ph[0][2 * ks];
            a[1] = ph[1][2 * ks];
            a[2] = ph[0][2 * ks + 1];
            a[3] = ph[1][2 * ks + 1];
#pragma unroll
            for (int nt = 0; nt < 4; nt++) mma_f16(oacc[nt], a, bv[nt]);
            mma_f16(oacc[4], a, bones);
        }
    }

    // ---- epilogue
    const int b = bh >> 3, h = bh & 7;
    const int r0 = rowb + gq;
    const int r1 = r0 + 8;
    float* o0 = &g_O[(size_t)(b * Tt + r0) * HD + h * 32];
    float* o1 = &g_O[(size_t)(b * Tt + r1) * HD + h * 32];
#pragma unroll
    for (int nt = 0; nt < 4; nt++) {
        const int cc = nt * 8 + 2 * l;
        atomicAdd(o0 + cc,     oacc[nt][0]);
        atomicAdd(o0 + cc + 1, oacc[nt][1]);
        atomicAdd(o1 + cc,     oacc[nt][2]);
        atomicAdd(o1 + cc + 1, oacc[nt][3]);
    }
    if (l == 0) {
        atomicAdd(&g_L[(size_t)(b * Tt + r0) * Hh + h], oacc[4][0]);
        atomicAdd(&g_L[(size_t)(b * Tt + r1) * Hh + h], oacc[4][2]);
    }
}

// ---------------------------------------------------------------------------
// Kernel 3: out = (O / l) @ Wo.
// ---------------------------------------------------------------------------
__global__ __launch_bounds__(256) void out_mma_kernel(float* __restrict__ out)
{
    extern __shared__ __half osm[];
    __half* As  = osm;                 // [64][264]
    __half* Wst = osm + 64 * 264;      // [64 n][264 k]
    float*  rls = reinterpret_cast<float*>(osm + 2 * 64 * 264);  // [64][8]

    const int m0 = blockIdx.x * 64;
    const int n0 = blockIdx.y * 64;

    const int tid  = threadIdx.x;
    const int wid  = tid >> 5;
    const int wm   = wid & 3;
    const int wh   = wid >> 2;
    const int lane = tid & 31;
    const int gq   = lane >> 2;
    const int l    = lane & 3;
    const int r8   = lane & 7;
    const int qg   = lane >> 3;

    const uint32_t as_addr  = smem_u32(As);
    const uint32_t wst_addr = smem_u32(Wst);

    for (int i = tid; i < 64 * 32; i += 256) {
        int n = i >> 5, seg = i & 31;
        cp16(wst_addr + n * 528 + seg * 16, g_WoT + (size_t)(n0 + n) * HD + seg * 8);
    }
    CP_COMMIT();

    for (int i = tid; i < 64 * 8; i += 256)
        rls[i] = frcp(g_L[(size_t)(m0 + (i >> 3)) * Hh + (i & 7)]);
    __syncthreads();

    for (int i = tid; i < 64 * 64; i += 256) {
        int r = i >> 6, c4 = (i & 63) * 4;
        float rl = rls[r * 8 + (c4 >> 5)];
        float4 v = *reinterpret_cast<const float4*>(&g_O[(size_t)(m0 + r) * HD + c4]);
        uint2 u = make_uint2(pack_h2(v.x * rl, v.y * rl), pack_h2(v.z * rl, v.w * rl));
        *reinterpret_cast<uint2*>(&As[r * 264 + c4]) = u;
    }
    CP_WAIT0();
    __syncthreads();

    const uint32_t arow_off = (uint32_t)(((qg & 1) * 8 + r8) * 528 + (qg >> 1) * 16);
    const uint32_t brow_off = (uint32_t)(((qg >> 1) * 8 + r8) * 528 + (qg & 1) * 16);
    const uint32_t ab = as_addr + wm * 8448 + arow_off;
    const uint32_t bb = wst_addr + wh * 16896 + brow_off;

    float sc[4][4] = {};
#pragma unroll
    for (int ks = 0; ks < 16; ks++) {
        uint32_t a[4];
        ldsm4(a[0], a[1], a[2], a[3], ab + ks * 32);
        uint32_t b[4][2];
#pragma unroll
        for (int p = 0; p < 2; p++)
            ldsm4(b[2 * p][0], b[2 * p][1], b[2 * p + 1][0], b[2 * p + 1][1],
                  bb + p * 8448 + ks * 32);
#pragma unroll
        for (int nt = 0; nt < 4; nt++) mma_f16(sc[nt], a, b[nt]);
    }

    const int m = m0 + wm * 16 + gq;
#pragma unroll
    for (int nt = 0; nt < 4; nt++) {
        const int n = n0 + wh * 32 + nt * 8 + 2 * l;
        *reinterpret_cast<float2*>(&out[(size_t)m * HD + n]) =
            make_float2(sc[nt][0], sc[nt][1]);
        *reinterpret_cast<float2*>(&out[(size_t)(m + 8) * HD + n]) =
            make_float2(sc[nt][2], sc[nt][3]);
    }
}

// ---------------------------------------------------------------------------
extern "C" void kernel_launch(void* const* d_in, const int* in_sizes, int n_in,
                              void* d_out, int out_size)
{
    const float* x  = (const float*)d_in[0];
    const float* Wq = (const float*)d_in[1];
    const float* Wk = (const float*)d_in[2];
    const float* Wv = (const float*)d_in[3];
    const float* Wo = (const float*)d_in[4];
    float* out = (float*)d_out;

    (void)in_sizes; (void)n_in; (void)out_size;

    const int smem_proj = (256 * 72 + 64 * 72) * 2;                    // 46080
    const int smem_attn = (128 * 40 + 2 * 64 * 40 + 2 * 32 * 72) * 2;  // 29696
    const int smem_out  = 2 * 64 * 264 * 2 + 64 * 8 * 4;               // 69632

    cudaFuncSetAttribute(proj_mma_kernel, cudaFuncAttributeMaxDynamicSharedMemorySize, smem_proj);
    cudaFuncSetAttribute(attn_mma_kernel, cudaFuncAttributeMaxDynamicSharedMemorySize, smem_attn);
    cudaFuncSetAttribute(out_mma_kernel,  cudaFuncAttributeMaxDynamicSharedMemorySize, smem_out);

    prep_kernel<<<NZERO_BLK + 64, 256>>>(Wo);
    proj_mma_kernel<<<dim3(BT / 256, HD / 64, 3), 256, smem_proj>>>(x, Wq, Wk, Wv);
    attn_mma_kernel<<<dim3(80, Bb * Hh), 256, smem_attn>>>();
    out_mma_kernel<<<dim3(BT / 64, HD / 64), 256, smem_out>>>(out);
}

// round 12
// speedup vs baseline: 1.1018x; 1.1018x over previous
#include <cuda_runtime.h>
#include <cuda_fp16.h>
#include <cstdint>

#define Bb 2
#define Tt 4096
#define Hh 8
#define Dd 32
#define HD 256
#define XD 128
#define TOKD 64
#define BT (Bb*Tt)

#define NZERO_F4 ((BT*HD + BT*Hh) / 4)          // 540672
#define NZERO_BLK ((NZERO_F4 + 255) / 256)      // 2112

__device__ __half g_Qh[Bb*Hh*Tt*Dd];
__device__ __half g_Kh[Bb*Hh*Tt*Dd];
__device__ __half g_Vt[Bb*Hh*Dd*Tt];
__device__ float  g_O[BT*HD];
__device__ float  g_L[BT*Hh];
__device__ __half g_WoT[HD*HD];

__device__ __forceinline__ uint32_t pack_h2(float lo, float hi) {
    __half2 h = __floats2half2_rn(lo, hi);
    return *reinterpret_cast<uint32_t*>(&h);
}
__device__ __forceinline__ uint32_t h2exp2(uint32_t x) {
    uint32_t y;
    asm("ex2.approx.f16x2 %0, %1;" : "=r"(y) : "r"(x));
    return y;
}
__device__ __forceinline__ float frcp(float x) {
    float y;
    asm("rcp.approx.ftz.f32 %0, %1;" : "=f"(y) : "f"(x));
    return y;
}
__device__ __forceinline__ void mma_f16(float* d, const uint32_t* a, const uint32_t* b) {
    asm volatile(
        "mma.sync.aligned.m16n8k16.row.col.f32.f16.f16.f32 "
        "{%0,%1,%2,%3}, {%4,%5,%6,%7}, {%8,%9}, {%0,%1,%2,%3};"
        : "+f"(d[0]), "+f"(d[1]), "+f"(d[2]), "+f"(d[3])
        : "r"(a[0]), "r"(a[1]), "r"(a[2]), "r"(a[3]), "r"(b[0]), "r"(b[1]));
}
__device__ __forceinline__ void ldsm4(uint32_t& r0, uint32_t& r1, uint32_t& r2, uint32_t& r3,
                                      uint32_t addr) {
    asm volatile("ldmatrix.sync.aligned.m8n8.x4.shared.b16 {%0,%1,%2,%3}, [%4];"
                 : "=r"(r0), "=r"(r1), "=r"(r2), "=r"(r3) : "r"(addr));
}
__device__ __forceinline__ uint32_t smem_u32(const void* p) {
    uint32_t a;
    asm("{ .reg .u64 t; cvta.to.shared.u64 t, %1; cvt.u32.u64 %0, t; }" : "=r"(a) : "l"(p));
    return a;
}
__device__ __forceinline__ void cp16(uint32_t d, const void* s) {
    asm volatile("cp.async.cg.shared.global [%0], [%1], 16;" :: "r"(d), "l"(s));
}
#define CP_COMMIT() asm volatile("cp.async.commit_group;" ::: "memory")
#define CP_WAIT0()  asm volatile("cp.async.wait_group 0;" ::: "memory")
#define CP_WAIT1()  asm volatile("cp.async.wait_group 1;" ::: "memory")

// ---------------------------------------------------------------------------
// Kernel 0: zero O/L + transpose Wo into g_WoT (half).
// ---------------------------------------------------------------------------
__global__ __launch_bounds__(256) void prep_kernel(const float* __restrict__ Wo)
{
    __shared__ __half t[32][34];
    const unsigned bid = blockIdx.x;
    const int tid = threadIdx.x;

    if (bid < (unsigned)NZERO_BLK) {
        const unsigned i = bid * 256u + tid;
        const float4 z = make_float4(0.f, 0.f, 0.f, 0.f);
        if (i < (BT * HD / 4)) reinterpret_cast<float4*>(g_O)[i] = z;
        else if (i < NZERO_F4) reinterpret_cast<float4*>(g_L)[i - BT * HD / 4] = z;
        return;
    }
    const int b2 = bid - NZERO_BLK;
    const int bx = (b2 & 7) * 32, by = (b2 >> 3) * 32;
    for (int i = tid; i < 1024; i += 256) {
        int r = i >> 5, c = i & 31;
        t[r][c] = __float2half_rn(Wo[(size_t)(by + r) * HD + bx + c]);
    }
    __syncthreads();
    for (int i = tid; i < 1024; i += 256) {
        int r = i >> 5, c = i & 31;
        g_WoT[(size_t)(bx + r) * HD + by + c] = t[c][r];
    }
}

// ---------------------------------------------------------------------------
// Kernel 1: projections via fp16 m16n8k16.
// ---------------------------------------------------------------------------
__global__ __launch_bounds__(256) void proj_mma_kernel(
    const float* __restrict__ x,
    const float* __restrict__ Wq,
    const float* __restrict__ Wk,
    const float* __restrict__ Wv)
{
    extern __shared__ __half psm[];
    __half* Xh  = psm;               // [256][72]
    __half* Wst = psm + 256 * 72;    // [64 n][72 k]

    const int z = blockIdx.z;
    const float* __restrict__ W = (z == 0) ? Wq : (z == 1) ? Wk : Wv;
    const int xoff = (z == 2) ? 0 : TOKD;

    const int m0 = blockIdx.x * 256;
    const int n0 = blockIdx.y * 64;

    const int tid  = threadIdx.x;
    const int wid  = tid >> 5;
    const int lane = tid & 31;
    const int gq   = lane >> 2;
    const int l    = lane & 3;

    for (int i = tid; i < 256 * 16; i += 256) {
        int r = i >> 4, c4 = (i & 15) * 4;
        float4 v = *reinterpret_cast<const float4*>(&x[(size_t)(m0 + r) * XD + xoff + c4]);
        uint2 u = make_uint2(pack_h2(v.x, v.y), pack_h2(v.z, v.w));
        *reinterpret_cast<uint2*>(&Xh[r * 72 + c4]) = u;
    }
    for (int i = tid; i < 64 * 16; i += 256) {
        int k = i >> 4, n4 = (i & 15) * 4;
        float4 w = *reinterpret_cast<const float4*>(&W[(size_t)k * HD + n0 + n4]);
        Wst[(n4 + 0) * 72 + k] = __float2half_rn(w.x);
        Wst[(n4 + 1) * 72 + k] = __float2half_rn(w.y);
        Wst[(n4 + 2) * 72 + k] = __float2half_rn(w.z);
        Wst[(n4 + 3) * 72 + k] = __float2half_rn(w.w);
    }
    __syncthreads();

    float sc[2][8][4] = {};
    const int rb = wid * 32;
#pragma unroll
    for (int ks = 0; ks < 4; ks++) {
        const int kk = ks * 16 + 2 * l;
        uint32_t b[8][2];
#pragma unroll
        for (int nt = 0; nt < 8; nt++) {
            b[nt][0] = *reinterpret_cast<const uint32_t*>(&Wst[(nt * 8 + gq) * 72 + kk]);
            b[nt][1] = *reinterpret_cast<const uint32_t*>(&Wst[(nt * 8 + gq) * 72 + kk + 8]);
        }
#pragma unroll
        for (int mt = 0; mt < 2; mt++) {
            const int r0 = rb + mt * 16;
            uint32_t a[4];
            a[0] = *reinterpret_cast<const uint32_t*>(&Xh[(r0 + gq) * 72 + kk]);
            a[1] = *reinterpret_cast<const uint32_t*>(&Xh[(r0 + 8 + gq) * 72 + kk]);
            a[2] = *reinterpret_cast<const uint32_t*>(&Xh[(r0 + gq) * 72 + kk + 8]);
            a[3] = *reinterpret_cast<const uint32_t*>(&Xh[(r0 + 8 + gq) * 72 + kk + 8]);
#pragma unroll
            for (int nt = 0; nt < 8; nt++) mma_f16(sc[mt][nt], a, b[nt]);
        }
    }

    if (z == 0) {
        const float qs = 0.17677669529663687f * 1.4426950408889634f;
#pragma unroll
        for (int mt = 0; mt < 2; mt++)
#pragma unroll
            for (int nt = 0; nt < 8; nt++)
#pragma unroll
                for (int e = 0; e < 4; e++) sc[mt][nt][e] *= qs;
    }

    if (z < 2) {
        __half* __restrict__ gh = (z == 0) ? g_Qh : g_Kh;
#pragma unroll
        for (int mt = 0; mt < 2; mt++) {
            const int m = m0 + rb + mt * 16 + gq;
            const int b0 = m >> 12, t0 = m & (Tt - 1);
            const int t1 = (m + 8) & (Tt - 1);
#pragma unroll
            for (int nt = 0; nt < 8; nt++) {
                const int n = n0 + nt * 8 + 2 * l;
                const int h = n >> 5, d = n & 31;
                __half2 w0 = __floats2half2_rn(sc[mt][nt][0], sc[mt][nt][1]);
                __half2 w1 = __floats2half2_rn(sc[mt][nt][2], sc[mt][nt][3]);
                *reinterpret_cast<__half2*>(&gh[(((size_t)(b0 * Hh + h)) * Tt + t0) * Dd + d]) = w0;
                *reinterpret_cast<__half2*>(&gh[(((size_t)(b0 * Hh + h)) * Tt + t1) * Dd + d]) = w1;
            }
        }
    } else {
#pragma unroll
        for (int mt = 0; mt < 2; mt++) {
            const int m = m0 + rb + mt * 16 + gq;
            const int b0 = m >> 12, t0 = m & (Tt - 1);
            const int t1 = (m + 8) & (Tt - 1);
#pragma unroll
            for (int nt = 0; nt < 8; nt++) {
                const int n = n0 + nt * 8 + 2 * l;
                const int h = n >> 5, d = n & 31;
                __half* base = &g_Vt[(size_t)(b0 * Hh + h) * Dd * Tt];
                base[(size_t)(d    ) * Tt + t0] = __float2half_rn(sc[mt][nt][0]);
                base[(size_t)(d + 1) * Tt + t0] = __float2half_rn(sc[mt][nt][1]);
                base[(size_t)(d    ) * Tt + t1] = __float2half_rn(sc[mt][nt][2]);
                base[(size_t)(d + 1) * Tt + t1] = __float2half_rn(sc[mt][nt][3]);
            }
        }
    }
}

// ---------------------------------------------------------------------------
// Kernel 2: chunked fp16 attention, 128-wide KV tiles (2 halves per tile).
// ---------------------------------------------------------------------------
__global__ __launch_bounds__(256, 2) void attn_mma_kernel()
{
    extern __shared__ __half hsm[];
    __half* Qs  = hsm;                  // [128][40]   (80B rows)
    __half* KsB = hsm + 128 * 40;       // 2 x [128][40]
    __half* VtB = KsB + 2 * 128 * 40;   // 2 x [32][136] (272B rows)

    const int cid = 79 - blockIdx.x;
    int qt, ch;
    if (cid < 8)       { qt = cid;                 ch = 0; }
    else if (cid < 24) { qt = 8 + ((cid - 8) >> 1);  ch = (cid - 8) & 1; }
    else if (cid < 48) { qt = 16 + (cid - 24) / 3;   ch = (cid - 24) % 3; }
    else               { qt = 24 + ((cid - 48) >> 2); ch = (cid - 48) & 3; }

    const int bh = blockIdx.y;
    const int q0 = qt * 128;
    const int nkv = qt + 1;                       // 128-kv tiles
    const int ntiles = min(8, nkv - ch * 8);

    const __half* __restrict__ Qp = g_Qh + (size_t)bh * Tt * Dd;
    const __half* __restrict__ Kp = g_Kh + (size_t)bh * Tt * Dd;
    const __half* __restrict__ Vp = g_Vt + (size_t)bh * Dd * Tt;

    const int tid  = threadIdx.x;
    const int wid  = tid >> 5;
    const int lane = tid & 31;
    const int gq   = lane >> 2;
    const int l    = lane & 3;
    const int r8   = lane & 7;
    const int qg   = lane >> 3;

    const uint32_t qs_addr = smem_u32(Qs);
    const uint32_t ks_addr = smem_u32(KsB);
    const uint32_t vt_addr = smem_u32(VtB);

    const uint32_t qrow_off = (uint32_t)(((qg & 1) * 8 + r8) * 80 + (qg >> 1) * 16);
    const uint32_t krow_off = (uint32_t)(((qg >> 1) * 8 + r8) * 80 + (qg & 1) * 16);
    const uint32_t vrow_off = (uint32_t)(((qg >> 1) * 8 + r8) * 272 + (qg & 1) * 16);

    // Q stage (2 uint4 per thread)
    for (int i = tid; i < 128 * 4; i += 256) {
        int r = i >> 2, seg = i & 3;
        uint4 v = *reinterpret_cast<const uint4*>(&Qp[(size_t)(q0 + r) * Dd + seg * 8]);
        *reinterpret_cast<uint4*>(&Qs[r * 40 + seg * 8]) = v;
    }

    // prefetch tile 0 -> buf 0
    {
        const int k0 = ch * 1024;
#pragma unroll
        for (int j = 0; j < 2; j++) {
            int idx = tid + j * 256;
            int row = idx >> 2, seg = idx & 3;
            cp16(ks_addr + row * 80 + seg * 16, Kp + (size_t)(k0 + row) * Dd + seg * 8);
            int d = idx >> 4, seg16 = idx & 15;
            cp16(vt_addr + d * 272 + seg16 * 16, Vp + (size_t)d * Tt + k0 + seg16 * 8);
        }
        CP_COMMIT();
    }

    __syncthreads();   // Q visible

    uint32_t qa[2][4];
#pragma unroll
    for (int ks = 0; ks < 2; ks++)
        ldsm4(qa[ks][0], qa[ks][1], qa[ks][2], qa[ks][3],
              qs_addr + (wid * 16) * 80 + qrow_off + ks * 32);

    const uint32_t bone = (gq == 0) ? 0x3C003C00u : 0u;
    const uint32_t bones[2] = { bone, bone };

    float oacc[5][4] = {};
    const int rowb = q0 + wid * 16;

    for (int it = 0; it < ntiles; it++) {
        __syncthreads();
        if (it + 1 < ntiles) {
            const int k0n = ch * 1024 + (it + 1) * 128;
            const int buf = (it + 1) & 1;
#pragma unroll
            for (int j = 0; j < 2; j++) {
                int idx = tid + j * 256;
                int row = idx >> 2, seg = idx & 3;
                cp16(ks_addr + buf * 10240 + row * 80 + seg * 16,
                     Kp + (size_t)(k0n + row) * Dd + seg * 8);
                int d = idx >> 4, seg16 = idx & 15;
                cp16(vt_addr + buf * 8704 + d * 272 + seg16 * 16,
                     Vp + (size_t)d * Tt + k0n + seg16 * 8);
            }
            CP_COMMIT();
            CP_WAIT1();
        } else {
            CP_WAIT0();
        }
        __syncthreads();

        const int k0t = ch * 1024 + it * 128;
        const uint32_t kbase = ks_addr + (it & 1) * 10240 + krow_off;
        const uint32_t vbase = vt_addr + (it & 1) * 8704 + vrow_off;

#pragma unroll
        for (int half = 0; half < 2; half++) {
            const int k0h = k0t + half * 64;
            if (k0h > rowb + 15) continue;   // fully above diagonal for this warp

            const uint32_t kb = kbase + half * (64 * 80);
            const uint32_t vb = vbase + half * 128;   // 64 kv halves = 128 bytes into V row

            // ---- S = Q @ K^T (64 cols)
            float sc[8][4] = {};
#pragma unroll
            for (int ks = 0; ks < 2; ks++) {
                uint32_t bk[8][2];
#pragma unroll
                for (int p = 0; p < 4; p++)
                    ldsm4(bk[2 * p][0], bk[2 * p][1], bk[2 * p + 1][0], bk[2 * p + 1][1],
                          kb + p * 1280 + ks * 32);
#pragma unroll
                for (int nt = 0; nt < 8; nt++) mma_f16(sc[nt], qa[ks], bk[nt]);
            }

            // ---- softmax: p = 2^s via f16x2
            uint32_t ph[2][8];
            if (k0h + 63 <= rowb) {
#pragma unroll
                for (int nt = 0; nt < 8; nt++) {
                    ph[0][nt] = h2exp2(pack_h2(sc[nt][0], sc[nt][1]));
                    ph[1][nt] = h2exp2(pack_h2(sc[nt][2], sc[nt][3]));
                }
            } else {
                const int r0 = rowb + gq, r1 = rowb + 8 + gq;
#pragma unroll
                for (int nt = 0; nt < 8; nt++) {
                    const int c0 = k0h + nt * 8 + 2 * l;
                    float f0 = (c0     <= r0) ? sc[nt][0] : -1e30f;
                    float f1 = (c0 + 1 <= r0) ? sc[nt][1] : -1e30f;
                    float f2 = (c0     <= r1) ? sc[nt][2] : -1e30f;
                    float f3 = (c0 + 1 <= r1) ? sc[nt][3] : -1e30f;
                    ph[0][nt] = h2exp2(pack_h2(f0, f1));
                    ph[1][nt] = h2exp2(pack_h2(f2, f3));
                }
            }

            // ---- O += P @ [V | 1]   (V frag: p steps 16 d-rows = 16*272 bytes)
#pragma unroll
            for (int ks = 0; ks < 4; ks++) {
                uint32_t bv[4][2];
#pragma unroll
                for (int p = 0; p < 2; p++)
                    ldsm4(bv[2 * p][0], bv[2 * p][1], bv[2 * p + 1][0], bv[2 * p + 1][1],
                          vb + p * 4352 + ks * 32);
                uint32_t a[4];
                a[0] = ph[0][2 * ks];
                a[1] = ph[1][2 * ks];
                a[2] = ph[0][2 * ks + 1];
                a[3] = ph[1][2 * ks + 1];
#pragma unroll
                for (int nt = 0; nt < 4; nt++) mma_f16(oacc[nt], a, bv[nt]);
                mma_f16(oacc[4], a, bones);
            }
        }
    }

    // ---- epilogue
    const int b = bh >> 3, h = bh & 7;
    const int r0 = rowb + gq;
    const int r1 = r0 + 8;
    float* o0 = &g_O[(size_t)(b * Tt + r0) * HD + h * 32];
    float* o1 = &g_O[(size_t)(b * Tt + r1) * HD + h * 32];
#pragma unroll
    for (int nt = 0; nt < 4; nt++) {
        const int cc = nt * 8 + 2 * l;
        atomicAdd(o0 + cc,     oacc[nt][0]);
        atomicAdd(o0 + cc + 1, oacc[nt][1]);
        atomicAdd(o1 + cc,     oacc[nt][2]);
        atomicAdd(o1 + cc + 1, oacc[nt][3]);
    }
    if (l == 0) {
        atomicAdd(&g_L[(size_t)(b * Tt + r0) * Hh + h], oacc[4][0]);
        atomicAdd(&g_L[(size_t)(b * Tt + r1) * Hh + h], oacc[4][2]);
    }
}

// ---------------------------------------------------------------------------
// Kernel 3: out = (O / l) @ Wo. Single barrier; per-element L reload (cached).
// ---------------------------------------------------------------------------
__global__ __launch_bounds__(256) void out_mma_kernel(float* __restrict__ out)
{
    extern __shared__ __half osm[];
    __half* As  = osm;                 // [64][264]
    __half* Wst = osm + 64 * 264;      // [64 n][264 k]

    const int m0 = blockIdx.x * 64;
    const int n0 = blockIdx.y * 64;

    const int tid  = threadIdx.x;
    const int wid  = tid >> 5;
    const int wm   = wid & 3;
    const int wh   = wid >> 2;
    const int lane = tid & 31;
    const int gq   = lane >> 2;
    const int l    = lane & 3;
    const int r8   = lane & 7;
    const int qg   = lane >> 3;

    const uint32_t as_addr  = smem_u32(As);
    const uint32_t wst_addr = smem_u32(Wst);

    for (int i = tid; i < 64 * 32; i += 256) {
        int n = i >> 5, seg = i & 31;
        cp16(wst_addr + n * 528 + seg * 16, g_WoT + (size_t)(n0 + n) * HD + seg * 8);
    }
    CP_COMMIT();

#pragma unroll
    for (int s = 0; s < 16; s++) {
        int idx = tid + s * 256;
        int r = idx >> 6, c4 = (idx & 63) * 4;
        float rl = frcp(g_L[(size_t)(m0 + r) * Hh + (c4 >> 5)]);
        float4 v = *reinterpret_cast<const float4*>(&g_O[(size_t)(m0 + r) * HD + c4]);
        uint2 u = make_uint2(pack_h2(v.x * rl, v.y * rl), pack_h2(v.z * rl, v.w * rl));
        *reinterpret_cast<uint2*>(&As[r * 264 + c4]) = u;
    }
    CP_WAIT0();
    __syncthreads();

    const uint32_t arow_off = (uint32_t)(((qg & 1) * 8 + r8) * 528 + (qg >> 1) * 16);
    const uint32_t brow_off = (uint32_t)(((qg >> 1) * 8 + r8) * 528 + (qg & 1) * 16);
    const uint32_t ab = as_addr + wm * 8448 + arow_off;
    const uint32_t bb = wst_addr + wh * 16896 + brow_off;

    float sc[4][4] = {};
#pragma unroll
    for (int ks = 0; ks < 16; ks++) {
        uint32_t a[4];
        ldsm4(a[0], a[1], a[2], a[3], ab + ks * 32);
        uint32_t b[4][2];
#pragma unroll
        for (int p = 0; p < 2; p++)
            ldsm4(b[2 * p][0], b[2 * p][1], b[2 * p + 1][0], b[2 * p + 1][1],
                  bb + p * 8448 + ks * 32);
#pragma unroll
        for (int nt = 0; nt < 4; nt++) mma_f16(sc[nt], a, b[nt]);
    }

    const int m = m0 + wm * 16 + gq;
#pragma unroll
    for (int nt = 0; nt < 4; nt++) {
        const int n = n0 + wh * 32 + nt * 8 + 2 * l;
        *reinterpret_cast<float2*>(&out[(size_t)m * HD + n]) =
            make_float2(sc[nt][0], sc[nt][1]);
        *reinterpret_cast<float2*>(&out[(size_t)(m + 8) * HD + n]) =
            make_float2(sc[nt][2], sc[nt][3]);
    }
}

// ---------------------------------------------------------------------------
extern "C" void kernel_launch(void* const* d_in, const int* in_sizes, int n_in,
                              void* d_out, int out_size)
{
    const float* x  = (const float*)d_in[0];
    const float* Wq = (const float*)d_in[1];
    const float* Wk = (const float*)d_in[2];
    const float* Wv = (const float*)d_in[3];
    const float* Wo = (const float*)d_in[4];
    float* out = (float*)d_out;

    (void)in_sizes; (void)n_in; (void)out_size;

    const int smem_proj = (256 * 72 + 64 * 72) * 2;                     // 46080
    const int smem_attn = (128 * 40 + 2 * 128 * 40 + 2 * 32 * 136) * 2; // 48128
    const int smem_out  = 2 * 64 * 264 * 2;                             // 67584

    cudaFuncSetAttribute(proj_mma_kernel, cudaFuncAttributeMaxDynamicSharedMemorySize, smem_proj);
    cudaFuncSetAttribute(attn_mma_kernel, cudaFuncAttributeMaxDynamicSharedMemorySize, smem_attn);
    cudaFuncSetAttribute(out_mma_kernel,  cudaFuncAttributeMaxDynamicSharedMemorySize, smem_out);

    prep_kernel<<<NZERO_BLK + 64, 256>>>(Wo);
    proj_mma_kernel<<<dim3(BT / 256, HD / 64, 3), 256, smem_proj>>>(x, Wq, Wk, Wv);
    attn_mma_kernel<<<dim3(80, Bb * Hh), 256, smem_attn>>>();
    out_mma_kernel<<<dim3(BT / 64, HD / 64), 256, smem_out>>>(out);
}